// round 9
// baseline (speedup 1.0000x reference)
#include <cuda_runtime.h>
#include <math.h>
#include <stdint.h>

#define D_DIM    4096
#define E_DIM    64
#define TOPK     8
#define TILE_M   128
#define BK       32
#define NCH      (D_DIM / BK)     // 128
#define NTHREADS 256

// smem layout (bytes)
// XT: [2 buf][32 k][128 rows] f32, 4-row-group XOR swizzle    -> 2*16384
// BD: [2 buf][32 k][64 e] f32 (un-duplicated), group swizzle  -> 2*8192
// PS: partial sumsq [128 rows][8 slots] f32                   -> 4096
// RS: inv norm [128] f32
#define XT_OFF   0
#define XT_BUF   16384
#define BD_OFF   32768
#define BD_BUF   8192
#define PS_OFF   49152
#define RS_OFF   53248
#define SMEM_DYN 53760
// epilogue scratch (128*65*4 = 33280 B) reuses XT region

static __device__ __forceinline__ uint32_t smem_u32(const void* p) {
    uint32_t a;
    asm("{ .reg .u64 t; cvta.to.shared.u64 t, %1; cvt.u32.u64 %0, t; }" : "=r"(a) : "l"(p));
    return a;
}

static __device__ __forceinline__ void lds_v2u64(uint32_t addr,
                                                 unsigned long long& a,
                                                 unsigned long long& b) {
    asm volatile("ld.shared.v2.b64 {%0,%1}, [%2];" : "=l"(a), "=l"(b) : "r"(addr));
}

static __device__ __forceinline__ void lds_v4b32(uint32_t addr,
                                                 uint32_t& f0, uint32_t& f1,
                                                 uint32_t& f2, uint32_t& f3) {
    asm volatile("ld.shared.v4.b32 {%0,%1,%2,%3}, [%4];"
                 : "=r"(f0), "=r"(f1), "=r"(f2), "=r"(f3) : "r"(addr));
}

static __device__ __forceinline__ void fma2(unsigned long long& d,
                                            unsigned long long a,
                                            unsigned long long b) {
    asm("fma.rn.f32x2 %0, %1, %2, %0;" : "+l"(d) : "l"(a), "l"(b));
}

static __device__ __forceinline__ unsigned long long dup32(uint32_t u) {
    unsigned long long r;
    asm("mov.b64 %0, {%1, %1};" : "=l"(r) : "r"(u));
    return r;
}

static __device__ __forceinline__ float softplus_f(float v) {
    return fmaxf(v, 0.f) + log1pf(expf(-fabsf(v)));
}

__global__ __launch_bounds__(NTHREADS, 1)
void router_f32x2_v5_kernel(const float* __restrict__ x,
                            const float* __restrict__ sig,
                            float* __restrict__ out_w,
                            float* __restrict__ out_i,
                            float* __restrict__ out_res)
{
    extern __shared__ char sm[];
    const uint32_t sb = smem_u32(sm);

    const int tid  = threadIdx.x;
    const int wid  = tid >> 5;
    const int lane = tid & 31;
    const int row0 = blockIdx.x * TILE_M;

    // compute-side coords: warp tile 64 rows x 16 experts, thread 8 rows x 4 experts
    const int wy  = wid >> 2;          // row band (64 rows)
    const int wx  = wid & 3;           // expert band (16 experts)
    const int ey  = lane & 7;
    const int ex  = lane >> 3;
    const int r4a = wy * 16 + ey;      // row4 group, g=0
    const int r4b = r4a + 8;           // row4 group, g=1
    const int eg0 = wx * 4 + ex;       // expert4 group
    const int e0  = eg0 * 4;           // first expert

    // loader coords: lanes span k (coalesced LDG, 4 lines/instr)
    const int lsub  = (tid >> 3) & 3;
    const int lkoff = tid & 7;

    unsigned long long acc[4][4];
#pragma unroll
    for (int a = 0; a < 4; a++)
#pragma unroll
        for (int j = 0; j < 4; j++) acc[a][j] = 0ull;

    float ss[4] = {0.f, 0.f, 0.f, 0.f};

    // prologue: chunk 0 loads (coalesced)
    float4 xv[4], sv[2];
#pragma unroll
    for (int i = 0; i < 4; i++)
        xv[i] = *((const float4*)x +
                  (size_t)(row0 + wid * 16 + i * 4 + lsub) * (D_DIM / 4) + lkoff);
#pragma unroll
    for (int i = 0; i < 2; i++)
        sv[i] = *((const float4*)sig +
                  (size_t)(wid * 8 + i * 4 + lsub) * (D_DIM / 4) + lkoff);

    for (int kc = 0; kc < NCH; kc++) {
        const int buf = kc & 1;

        // ---- store regs -> swizzled smem; fold sumsq from registers ----
        {
            float* xt = (float*)(sm + XT_OFF + buf * XT_BUF);
#pragma unroll
            for (int i = 0; i < 4; i++) {
                float4 v = xv[i];
                ss[i] = fmaf(v.x, v.x, fmaf(v.y, v.y,
                          fmaf(v.z, v.z, fmaf(v.w, v.w, ss[i]))));
                const int col4 = (wid * 4 + i) ^ lkoff;          // f(k) = (k>>2)&7 = lkoff
                const int bw = (lkoff * 4) * 128 + col4 * 4 + lsub;
                xt[bw]       = v.x;
                xt[bw + 128] = v.y;
                xt[bw + 256] = v.z;
                xt[bw + 384] = v.w;
            }
            float* bd = (float*)(sm + BD_OFF + buf * BD_BUF);
#pragma unroll
            for (int i = 0; i < 2; i++) {
                float4 v = sv[i];
                const int eg = wid * 2 + i;                      // = e>>2 (e&3 = lsub)
                const int bw = (lkoff * 4) * 64 + ((eg ^ lkoff) * 4) + lsub;
                bd[bw]       = v.x;
                bd[bw + 64]  = v.y;
                bd[bw + 128] = v.z;
                bd[bw + 192] = v.w;
            }
        }
        __syncthreads();

        // ---- prefetch next chunk (coalesced) ----
        if (kc + 1 < NCH) {
#pragma unroll
            for (int i = 0; i < 4; i++)
                xv[i] = *((const float4*)x +
                          (size_t)(row0 + wid * 16 + i * 4 + lsub) * (D_DIM / 4) +
                          (kc + 1) * 8 + lkoff);
#pragma unroll
            for (int i = 0; i < 2; i++)
                sv[i] = *((const float4*)sig +
                          (size_t)(wid * 8 + i * 4 + lsub) * (D_DIM / 4) +
                          (kc + 1) * 8 + lkoff);
        }

        // ---- compute: 32 k-steps, 3 LDS.128 + 4 dup-mov + 16 FMA2 each ----
        {
            const uint32_t ab = sb + XT_OFF + buf * XT_BUF;
            const uint32_t bb = sb + BD_OFF + buf * BD_BUF;
#pragma unroll
            for (int kf = 0; kf < 8; kf++) {
                const uint32_t a0o = (uint32_t)((r4a ^ kf) * 16);
                const uint32_t a1o = (uint32_t)((r4b ^ kf) * 16);
                const uint32_t bgo = (uint32_t)((eg0 ^ kf) * 16);
#pragma unroll
                for (int kj = 0; kj < 4; kj++) {
                    const uint32_t k = (uint32_t)(kf * 4 + kj);
                    unsigned long long a01, a23, a45, a67;
                    uint32_t f0, f1, f2, f3;
                    lds_v2u64(ab + k * 512u + a0o, a01, a23);
                    lds_v2u64(ab + k * 512u + a1o, a45, a67);
                    lds_v4b32(bb + k * 256u + bgo, f0, f1, f2, f3);
                    unsigned long long b0 = dup32(f0);
                    unsigned long long b1 = dup32(f1);
                    unsigned long long b2 = dup32(f2);
                    unsigned long long b3 = dup32(f3);
                    fma2(acc[0][0], a01, b0); fma2(acc[0][1], a01, b1);
                    fma2(acc[0][2], a01, b2); fma2(acc[0][3], a01, b3);
                    fma2(acc[1][0], a23, b0); fma2(acc[1][1], a23, b1);
                    fma2(acc[1][2], a23, b2); fma2(acc[1][3], a23, b3);
                    fma2(acc[2][0], a45, b0); fma2(acc[2][1], a45, b1);
                    fma2(acc[2][2], a45, b2); fma2(acc[2][3], a45, b3);
                    fma2(acc[3][0], a67, b0); fma2(acc[3][1], a67, b1);
                    fma2(acc[3][2], a67, b2); fma2(acc[3][3], a67, b3);
                }
            }
        }
        __syncthreads();
    }

    // ---- combine sumsq partials, inv norm ----
    float* pss = (float*)(sm + PS_OFF);
    float* rowsum = (float*)(sm + RS_OFF);
#pragma unroll
    for (int i = 0; i < 4; i++)
        pss[(wid * 16 + i * 4 + lsub) * 8 + lkoff] = ss[i];
    __syncthreads();
    if (tid < TILE_M) {
        float s = 0.f;
#pragma unroll
        for (int q = 0; q < 8; q++) s += pss[tid * 8 + q];
        rowsum[tid] = 1.f / fmaxf(sqrtf(s), 1e-12f);
    }
    __syncthreads();

    // ---- scale, write resonance, stash scaled rows in scratch ----
    float* scr = (float*)sm;      // [128][65]
#pragma unroll
    for (int g = 0; g < 2; g++) {
#pragma unroll
        for (int p = 0; p < 2; p++) {
            const int lr = wy * 64 + g * 32 + ey * 4 + 2 * p;
            const float s0 = 5.0f * rowsum[lr];
            const float s1 = 5.0f * rowsum[lr + 1];
            float lo[4], hi[4];
#pragma unroll
            for (int j = 0; j < 4; j++) {
                unsigned long long u = acc[g * 2 + p][j];
                lo[j] = __uint_as_float((uint32_t)u) * s0;
                hi[j] = __uint_as_float((uint32_t)(u >> 32)) * s1;
            }
            *(float4*)(out_res + (size_t)(row0 + lr) * E_DIM + e0) =
                make_float4(lo[0], lo[1], lo[2], lo[3]);
            *(float4*)(out_res + (size_t)(row0 + lr + 1) * E_DIM + e0) =
                make_float4(hi[0], hi[1], hi[2], hi[3]);
#pragma unroll
            for (int j = 0; j < 4; j++) {
                scr[lr * 65 + e0 + j]       = lo[j];
                scr[(lr + 1) * 65 + e0 + j] = hi[j];
            }
        }
    }
    __syncthreads();

    // ---- fused top-8 + softplus (threads 0..127, one row each) ----
    if (tid < TILE_M) {
        float vals[64];
#pragma unroll
        for (int c = 0; c < 64; c++) vals[c] = scr[tid * 65 + c];
        float* wp = out_w + (size_t)(row0 + tid) * TOPK;
        float* ip = out_i + (size_t)(row0 + tid) * TOPK;
#pragma unroll
        for (int it = 0; it < TOPK; it++) {
            float best = vals[0];
            int bi = 0;
#pragma unroll
            for (int c = 1; c < 64; c++) {
                if (vals[c] > best) { best = vals[c]; bi = c; }
            }
            vals[bi] = -INFINITY;
            wp[it] = softplus_f(best);
            ip[it] = (float)bi;
        }
    }
}

extern "C" void kernel_launch(void* const* d_in, const int* in_sizes, int n_in,
                              void* d_out, int out_size)
{
    const float* x   = (const float*)d_in[0];
    const float* sig = (const float*)d_in[1];
    const int n_rows = in_sizes[0] / D_DIM;   // 16384

    float* out = (float*)d_out;
    float* out_w   = out;
    float* out_i   = out + (size_t)n_rows * TOPK;
    float* out_res = out + (size_t)n_rows * TOPK * 2;

    cudaFuncSetAttribute(router_f32x2_v5_kernel,
                         cudaFuncAttributeMaxDynamicSharedMemorySize, SMEM_DYN);

    router_f32x2_v5_kernel<<<n_rows / TILE_M, NTHREADS, SMEM_DYN>>>(
        x, sig, out_w, out_i, out_res);
}